// round 4
// baseline (speedup 1.0000x reference)
#include <cuda_runtime.h>
#include <cstdint>

#define BSZ 64
#define TM 128
#define NTHREADS 256
#define ROWSTRIDE 68            // floats per row (64 + 4 pad) -> conflict-free ldmatrix
#define A_FLOATS (TM * ROWSTRIDE)     // 8704
#define B_FLOATS (BSZ * ROWSTRIDE)    // 4352
#define BUF_FLOATS (A_FLOATS + B_FLOATS)
#define SMEM_BYTES (2 * BUF_FLOATS * 4)   // 104448

// ---------------------------------------------------------------------------
// CSR scratch in device globals (no allocations allowed).
// ---------------------------------------------------------------------------
__device__ int g_start[257];
__device__ int g_list[16384];

__global__ void build_csr_kernel(const int* __restrict__ row_idx, int K, int nrows) {
    __shared__ int s_row[8192];
    __shared__ int s_cnt[256];
    int tid = threadIdx.x;
    for (int i = tid; i < K; i += blockDim.x) s_row[i] = row_idx[i];
    for (int i = tid; i < nrows; i += blockDim.x) s_cnt[i] = 0;
    __syncthreads();
    for (int i = tid; i < K; i += blockDim.x) atomicAdd(&s_cnt[s_row[i]], 1);
    __syncthreads();
    if (tid == 0) {
        int acc = 0;
        for (int r = 0; r < nrows; r++) { g_start[r] = acc; acc += s_cnt[r]; }
        g_start[nrows] = acc;
    }
    __syncthreads();
    // deterministic rank of k within its row
    for (int k = tid; k < K; k += blockDim.x) {
        int r = s_row[k];
        int rank = 0;
        for (int j = 0; j < k; j++) rank += (s_row[j] == r) ? 1 : 0;
        g_list[g_start[r] + rank] = k;
    }
}

// ---------------------------------------------------------------------------
// helpers
// ---------------------------------------------------------------------------
__device__ __forceinline__ uint32_t smem_to_u32(const void* p) {
    uint32_t a;
    asm("{ .reg .u64 t; cvta.to.shared.u64 t, %1; cvt.u32.u64 %0, t; }" : "=r"(a) : "l"(p));
    return a;
}

__device__ __forceinline__ unsigned int f2tf(unsigned int fbits) {
    unsigned int r;
    asm("cvt.rna.tf32.f32 %0, %1;" : "=r"(r) : "r"(fbits));
    return r;
}

#define CP_ASYNC16(dst, src) \
    asm volatile("cp.async.cg.shared.global [%0], [%1], 16;" :: "r"(dst), "l"(src) : "memory")
#define CP_COMMIT() asm volatile("cp.async.commit_group;" ::: "memory")
#define CP_WAIT(n)  asm volatile("cp.async.wait_group %0;" :: "n"(n) : "memory")

#define LDSM_X4(r0, r1, r2, r3, addr) \
    asm volatile("ldmatrix.sync.aligned.m8n8.x4.shared.b16 {%0,%1,%2,%3}, [%4];" \
                 : "=r"(r0), "=r"(r1), "=r"(r2), "=r"(r3) : "r"(addr))

__device__ __forceinline__ void mma_tf32(float* c, const unsigned int* a,
                                         unsigned int b0, unsigned int b1) {
    asm volatile(
        "mma.sync.aligned.m16n8k8.row.col.f32.tf32.tf32.f32 "
        "{%0,%1,%2,%3}, {%4,%5,%6,%7}, {%8,%9}, {%0,%1,%2,%3};\n"
        : "+f"(c[0]), "+f"(c[1]), "+f"(c[2]), "+f"(c[3])
        : "r"(a[0]), "r"(a[1]), "r"(a[2]), "r"(a[3]), "r"(b0), "r"(b1));
}

// ---------------------------------------------------------------------------
// Main kernel: CTA = (128-row x-tile, 64-col output block row).
// cp.async double-buffered raw-f32 smem tiles; ldmatrix.x4 fragment loads;
// cvt.rna.tf32 in registers; m16n8k8 tf32 mma. Warp grid 4(M) x 2(N),
// each warp computes m32 x n32.
// ---------------------------------------------------------------------------
__global__ void __launch_bounds__(NTHREADS)
bsl_kernel(const float* __restrict__ x, const float* __restrict__ blocks,
           const float* __restrict__ bias, const int* __restrict__ col_idx,
           float* __restrict__ y, int IN, int OUT) {
    extern __shared__ float smem[];
    const uint32_t sbase = smem_to_u32(smem);

    const int tid  = threadIdx.x;
    const int lane = tid & 31;
    const int warp = tid >> 5;
    const int wm   = warp & 3;    // 4 warps along M
    const int wn   = warp >> 2;   // 2 warps along N
    const int g    = lane >> 2;
    const int t    = lane & 3;

    const int n0   = blockIdx.x * TM;
    const int rblk = blockIdx.y;
    const int out0 = rblk * BSZ;

    const int beg = g_start[rblk];
    const int cnt = g_start[rblk + 1] - beg;

    float acc[2][4][4];
#pragma unroll
    for (int mf = 0; mf < 2; mf++)
#pragma unroll
        for (int nf = 0; nf < 4; nf++)
#pragma unroll
            for (int i = 0; i < 4; i++) acc[mf][nf][i] = 0.0f;

    // --- per-lane ldmatrix base offsets (bytes, within a buffer) ---
    // lane l supplies the address of one 16B row-segment:
    //   row_local = ((l>>3)&1)*8 + (l&7);  word = (l>>4)   (16B units)
    const int rl = ((lane >> 3) & 1) * 8 + (lane & 7);
    const int wb = lane >> 4;
    uint32_t a_off[2], b_off[2];
#pragma unroll
    for (int mf = 0; mf < 2; mf++)
        a_off[mf] = (uint32_t)((wm * 32 + mf * 16 + rl) * ROWSTRIDE + wb * 4) * 4;
#pragma unroll
    for (int h = 0; h < 2; h++)
        b_off[h] = (uint32_t)(A_FLOATS + (wn * 32 + h * 16 + rl) * ROWSTRIDE + wb * 4) * 4;

    const float* xb = x + (size_t)n0 * IN;

    // --- pipelined main loop ---
    // prologue: prefetch tile 0
    if (cnt > 0) {
        const int k0 = g_list[beg];
        const int c0 = col_idx[k0] * BSZ;
        const float* xs = xb + c0;
        const float* bs = blocks + (size_t)k0 * (BSZ * BSZ);
        const uint32_t buf = sbase;  // buffer 0
#pragma unroll
        for (int it = 0; it < 8; it++) {            // A: 2048 chunks / 256 thr
            int lin = tid + it * NTHREADS;
            int row = lin >> 4, w = lin & 15;
            CP_ASYNC16(buf + (uint32_t)(row * ROWSTRIDE + w * 4) * 4,
                       xs + (size_t)row * IN + w * 4);
        }
#pragma unroll
        for (int it = 0; it < 4; it++) {            // B: 1024 chunks
            int lin = tid + it * NTHREADS;
            int row = lin >> 4, w = lin & 15;
            CP_ASYNC16(buf + (uint32_t)(A_FLOATS + row * ROWSTRIDE + w * 4) * 4,
                       bs + row * BSZ + w * 4);
        }
        CP_COMMIT();
    }

    for (int i = 0; i < cnt; i++) {
        // prefetch tile i+1 into the other buffer
        if (i + 1 < cnt) {
            const int k1 = g_list[beg + i + 1];
            const int c1 = col_idx[k1] * BSZ;
            const float* xs = xb + c1;
            const float* bs = blocks + (size_t)k1 * (BSZ * BSZ);
            const uint32_t buf = sbase + ((i + 1) & 1) * (BUF_FLOATS * 4);
#pragma unroll
            for (int it = 0; it < 8; it++) {
                int lin = tid + it * NTHREADS;
                int row = lin >> 4, w = lin & 15;
                CP_ASYNC16(buf + (uint32_t)(row * ROWSTRIDE + w * 4) * 4,
                           xs + (size_t)row * IN + w * 4);
            }
#pragma unroll
            for (int it = 0; it < 4; it++) {
                int lin = tid + it * NTHREADS;
                int row = lin >> 4, w = lin & 15;
                CP_ASYNC16(buf + (uint32_t)(A_FLOATS + row * ROWSTRIDE + w * 4) * 4,
                           bs + row * BSZ + w * 4);
            }
            CP_COMMIT();
            CP_WAIT(1);          // tile i complete (tile i+1 may be in flight)
        } else {
            CP_WAIT(0);
        }
        __syncthreads();

        const uint32_t buf = sbase + (i & 1) * (BUF_FLOATS * 4);

        // ---- MMA over K=64 in 8 steps of k8 ----
#pragma unroll
        for (int kk = 0; kk < 8; kk++) {
            unsigned int ar[2][4], br[2][4];
#pragma unroll
            for (int mf = 0; mf < 2; mf++)
                LDSM_X4(ar[mf][0], ar[mf][1], ar[mf][2], ar[mf][3],
                        buf + a_off[mf] + kk * 32);
#pragma unroll
            for (int h = 0; h < 2; h++)
                LDSM_X4(br[h][0], br[h][1], br[h][2], br[h][3],
                        buf + b_off[h] + kk * 32);

            unsigned int a[2][4];
#pragma unroll
            for (int mf = 0; mf < 2; mf++)
#pragma unroll
                for (int r = 0; r < 4; r++) a[mf][r] = f2tf(ar[mf][r]);
            unsigned int b[2][4];
#pragma unroll
            for (int h = 0; h < 2; h++)
#pragma unroll
                for (int r = 0; r < 4; r++) b[h][r] = f2tf(br[h][r]);

            // nf mapping: nf = h*2 + s; b0 = b[h][s], b1 = b[h][s+2]
#pragma unroll
            for (int nf = 0; nf < 4; nf++) {
                const int h = nf >> 1, s = nf & 1;
#pragma unroll
                for (int mf = 0; mf < 2; mf++)
                    mma_tf32(acc[mf][nf], a[mf], b[h][s], b[h][s + 2]);
            }
        }
        __syncthreads();  // all warps done reading buf before it's overwritten
    }

    // ---- epilogue: y = acc + bias  (empty row -> bias only) ----
    if (cnt > 0) {
#pragma unroll
        for (int mf = 0; mf < 2; mf++) {
#pragma unroll
            for (int nf = 0; nf < 4; nf++) {
                int row = n0 + wm * 32 + mf * 16 + g;
                int col = out0 + wn * 32 + nf * 8 + 2 * t;
                float2 bv = *reinterpret_cast<const float2*>(bias + col);
                float2 lo, hi;
                lo.x = acc[mf][nf][0] + bv.x;
                lo.y = acc[mf][nf][1] + bv.y;
                hi.x = acc[mf][nf][2] + bv.x;
                hi.y = acc[mf][nf][3] + bv.y;
                *reinterpret_cast<float2*>(y + (size_t)row * OUT + col) = lo;
                *reinterpret_cast<float2*>(y + (size_t)(row + 8) * OUT + col) = hi;
            }
        }
    } else {
        // rows of y in this (n-tile, block-row): bias broadcast
        for (int r = warp; r < TM; r += 8) {
            int row = n0 + r;
            float* yrow = y + (size_t)row * OUT + out0;
            for (int c = lane * 2; c < BSZ; c += 64) {
                float2 bv = *reinterpret_cast<const float2*>(bias + out0 + c);
                *reinterpret_cast<float2*>(yrow + c) = bv;
            }
        }
    }
}

// ---------------------------------------------------------------------------
extern "C" void kernel_launch(void* const* d_in, const int* in_sizes, int n_in,
                              void* d_out, int out_size) {
    const float* x      = (const float*)d_in[0];
    const float* blocks = (const float*)d_in[1];
    const float* bias   = (const float*)d_in[2];
    const int*   row_i  = (const int*)d_in[3];
    const int*   col_i  = (const int*)d_in[4];
    float*       y      = (float*)d_out;

    const int K   = in_sizes[3];
    const int OUT = in_sizes[2];
    const int IN  = 4096;
    const int N   = in_sizes[0] / IN;
    const int nrows = OUT / BSZ;

    build_csr_kernel<<<1, 1024>>>(row_i, K, nrows);

    static int attr_set = 0;
    if (!attr_set) {
        cudaFuncSetAttribute(bsl_kernel,
                             cudaFuncAttributeMaxDynamicSharedMemorySize, SMEM_BYTES);
        attr_set = 1;
    }
    dim3 grid(N / TM, nrows);
    bsl_kernel<<<grid, NTHREADS, SMEM_BYTES>>>(x, blocks, bias, col_i, y, IN, OUT);
}

// round 5
// speedup vs baseline: 1.0815x; 1.0815x over previous
#include <cuda_runtime.h>
#include <cstdint>

#define BSZ 64
#define TM 128
#define NTHREADS 256
#define ROWSTRIDE 68            // floats per row (64 + 4 pad) -> conflict-free ldmatrix
#define A_FLOATS (TM * ROWSTRIDE)     // 8704
#define B_FLOATS (BSZ * ROWSTRIDE)    // 4352
#define BUF_FLOATS (A_FLOATS + B_FLOATS)
#define SMEM_BYTES (2 * BUF_FLOATS * 4)   // 104448

#define XN 4096
#define XIN 4096
#define KMAX 1024

// ---------------------------------------------------------------------------
// Device-global scratch (static, no allocations).
// ---------------------------------------------------------------------------
__device__ float g_xc[(size_t)XN * XIN];          // tf32-rounded x
__device__ float g_bc[(size_t)KMAX * BSZ * BSZ];  // tf32-rounded blocks
__device__ int g_start[257];
__device__ int g_list[16384];
__device__ int g_order[256];

// ---------------------------------------------------------------------------
// CSR build + longest-first row ordering (deterministic).
// ---------------------------------------------------------------------------
__global__ void build_csr_kernel(const int* __restrict__ row_idx, int K, int nrows) {
    __shared__ int s_row[8192];
    __shared__ int s_cnt[256];
    int tid = threadIdx.x;
    for (int i = tid; i < K; i += blockDim.x) s_row[i] = row_idx[i];
    for (int i = tid; i < nrows; i += blockDim.x) s_cnt[i] = 0;
    __syncthreads();
    for (int i = tid; i < K; i += blockDim.x) atomicAdd(&s_cnt[s_row[i]], 1);
    __syncthreads();
    if (tid == 0) {
        int acc = 0;
        for (int r = 0; r < nrows; r++) { g_start[r] = acc; acc += s_cnt[r]; }
        g_start[nrows] = acc;
    }
    __syncthreads();
    // deterministic rank of k within its row
    for (int k = tid; k < K; k += blockDim.x) {
        int r = s_row[k];
        int rank = 0;
        for (int j = 0; j < k; j++) rank += (s_row[j] == r) ? 1 : 0;
        g_list[g_start[r] + rank] = k;
    }
    // order rows by (count desc, row asc): heavy rows scheduled first
    if (tid < nrows) {
        int c = s_cnt[tid];
        int rank = 0;
        for (int r2 = 0; r2 < nrows; r2++) {
            int c2 = s_cnt[r2];
            rank += (c2 > c || (c2 == c && r2 < tid)) ? 1 : 0;
        }
        g_order[rank] = tid;
    }
}

// ---------------------------------------------------------------------------
// tf32 pre-conversion (RNA), float4 grid-stride.
// ---------------------------------------------------------------------------
__device__ __forceinline__ unsigned int f2tf(unsigned int fbits) {
    unsigned int r;
    asm("cvt.rna.tf32.f32 %0, %1;" : "=r"(r) : "r"(fbits));
    return r;
}

__global__ void __launch_bounds__(512)
cvt_kernel(const float* __restrict__ src, float* __restrict__ dst, int n4) {
    int idx = blockIdx.x * blockDim.x + threadIdx.x;
    int stride = gridDim.x * blockDim.x;
    const uint4* s = reinterpret_cast<const uint4*>(src);
    uint4* d = reinterpret_cast<uint4*>(dst);
    for (int i = idx; i < n4; i += stride) {
        uint4 v = s[i];
        v.x = f2tf(v.x); v.y = f2tf(v.y); v.z = f2tf(v.z); v.w = f2tf(v.w);
        d[i] = v;
    }
}

// ---------------------------------------------------------------------------
// helpers
// ---------------------------------------------------------------------------
__device__ __forceinline__ uint32_t smem_to_u32(const void* p) {
    uint32_t a;
    asm("{ .reg .u64 t; cvta.to.shared.u64 t, %1; cvt.u32.u64 %0, t; }" : "=r"(a) : "l"(p));
    return a;
}

#define CP_ASYNC16(dst, src) \
    asm volatile("cp.async.cg.shared.global [%0], [%1], 16;" :: "r"(dst), "l"(src) : "memory")
#define CP_COMMIT() asm volatile("cp.async.commit_group;" ::: "memory")
#define CP_WAIT(n)  asm volatile("cp.async.wait_group %0;" :: "n"(n) : "memory")

#define LDSM_X4(r0, r1, r2, r3, addr) \
    asm volatile("ldmatrix.sync.aligned.m8n8.x4.shared.b16 {%0,%1,%2,%3}, [%4];" \
                 : "=r"(r0), "=r"(r1), "=r"(r2), "=r"(r3) : "r"(addr))

__device__ __forceinline__ void mma_tf32(float* c, const unsigned int* a,
                                         unsigned int b0, unsigned int b1) {
    asm volatile(
        "mma.sync.aligned.m16n8k8.row.col.f32.tf32.tf32.f32 "
        "{%0,%1,%2,%3}, {%4,%5,%6,%7}, {%8,%9}, {%0,%1,%2,%3};\n"
        : "+f"(c[0]), "+f"(c[1]), "+f"(c[2]), "+f"(c[3])
        : "r"(a[0]), "r"(a[1]), "r"(a[2]), "r"(a[3]), "r"(b0), "r"(b1));
}

// ---------------------------------------------------------------------------
// Main GEMM: CTA = (128-row x-tile, 64-col output block row).
// Data already tf32-rounded in g_xc / g_bc: hot loop is LDSM -> mma only.
// ---------------------------------------------------------------------------
__global__ void __launch_bounds__(NTHREADS)
bsl_kernel(const float* __restrict__ bias, const int* __restrict__ col_idx,
           float* __restrict__ y, int IN, int OUT) {
    extern __shared__ float smem[];
    const uint32_t sbase = smem_to_u32(smem);

    const int tid  = threadIdx.x;
    const int lane = tid & 31;
    const int warp = tid >> 5;
    const int wm   = warp & 3;    // 4 warps along M
    const int wn   = warp >> 2;   // 2 warps along N
    const int g    = lane >> 2;
    const int t    = lane & 3;

    const int n0   = blockIdx.x * TM;
    const int rblk = g_order[blockIdx.y];
    const int out0 = rblk * BSZ;

    const int beg = g_start[rblk];
    const int cnt = g_start[rblk + 1] - beg;

    float acc[2][4][4];
#pragma unroll
    for (int mf = 0; mf < 2; mf++)
#pragma unroll
        for (int nf = 0; nf < 4; nf++)
#pragma unroll
            for (int i = 0; i < 4; i++) acc[mf][nf][i] = 0.0f;

    // per-lane ldmatrix base offsets (bytes, within a buffer)
    const int rl = ((lane >> 3) & 1) * 8 + (lane & 7);
    const int wb = lane >> 4;
    uint32_t a_off[2], b_off[2];
#pragma unroll
    for (int mf = 0; mf < 2; mf++)
        a_off[mf] = (uint32_t)((wm * 32 + mf * 16 + rl) * ROWSTRIDE + wb * 4) * 4;
#pragma unroll
    for (int h = 0; h < 2; h++)
        b_off[h] = (uint32_t)(A_FLOATS + (wn * 32 + h * 16 + rl) * ROWSTRIDE + wb * 4) * 4;

    const float* xb = g_xc + (size_t)n0 * IN;

    // prologue: prefetch tile 0
    if (cnt > 0) {
        const int k0 = g_list[beg];
        const int c0 = col_idx[k0] * BSZ;
        const float* xs = xb + c0;
        const float* bs = g_bc + (size_t)k0 * (BSZ * BSZ);
        const uint32_t buf = sbase;
#pragma unroll
        for (int it = 0; it < 8; it++) {
            int lin = tid + it * NTHREADS;
            int row = lin >> 4, w = lin & 15;
            CP_ASYNC16(buf + (uint32_t)(row * ROWSTRIDE + w * 4) * 4,
                       xs + (size_t)row * IN + w * 4);
        }
#pragma unroll
        for (int it = 0; it < 4; it++) {
            int lin = tid + it * NTHREADS;
            int row = lin >> 4, w = lin & 15;
            CP_ASYNC16(buf + (uint32_t)(A_FLOATS + row * ROWSTRIDE + w * 4) * 4,
                       bs + row * BSZ + w * 4);
        }
        CP_COMMIT();
    }

    for (int i = 0; i < cnt; i++) {
        if (i + 1 < cnt) {
            const int k1 = g_list[beg + i + 1];
            const int c1 = col_idx[k1] * BSZ;
            const float* xs = xb + c1;
            const float* bs = g_bc + (size_t)k1 * (BSZ * BSZ);
            const uint32_t buf = sbase + ((i + 1) & 1) * (BUF_FLOATS * 4);
#pragma unroll
            for (int it = 0; it < 8; it++) {
                int lin = tid + it * NTHREADS;
                int row = lin >> 4, w = lin & 15;
                CP_ASYNC16(buf + (uint32_t)(row * ROWSTRIDE + w * 4) * 4,
                           xs + (size_t)row * IN + w * 4);
            }
#pragma unroll
            for (int it = 0; it < 4; it++) {
                int lin = tid + it * NTHREADS;
                int row = lin >> 4, w = lin & 15;
                CP_ASYNC16(buf + (uint32_t)(A_FLOATS + row * ROWSTRIDE + w * 4) * 4,
                           bs + row * BSZ + w * 4);
            }
            CP_COMMIT();
            CP_WAIT(1);
        } else {
            CP_WAIT(0);
        }
        __syncthreads();

        const uint32_t buf = sbase + (i & 1) * (BUF_FLOATS * 4);

#pragma unroll
        for (int kk = 0; kk < 8; kk++) {
            unsigned int a[2][4], b[2][4];
#pragma unroll
            for (int mf = 0; mf < 2; mf++)
                LDSM_X4(a[mf][0], a[mf][1], a[mf][2], a[mf][3],
                        buf + a_off[mf] + kk * 32);
#pragma unroll
            for (int h = 0; h < 2; h++)
                LDSM_X4(b[h][0], b[h][1], b[h][2], b[h][3],
                        buf + b_off[h] + kk * 32);

#pragma unroll
            for (int nf = 0; nf < 4; nf++) {
                const int h = nf >> 1, s = nf & 1;
#pragma unroll
                for (int mf = 0; mf < 2; mf++)
                    mma_tf32(acc[mf][nf], a[mf], b[h][s], b[h][s + 2]);
            }
        }
        __syncthreads();
    }

    // epilogue
    if (cnt > 0) {
#pragma unroll
        for (int mf = 0; mf < 2; mf++) {
#pragma unroll
            for (int nf = 0; nf < 4; nf++) {
                int row = n0 + wm * 32 + mf * 16 + g;
                int col = out0 + wn * 32 + nf * 8 + 2 * t;
                float2 bv = *reinterpret_cast<const float2*>(bias + col);
                float2 lo, hi;
                lo.x = acc[mf][nf][0] + bv.x;
                lo.y = acc[mf][nf][1] + bv.y;
                hi.x = acc[mf][nf][2] + bv.x;
                hi.y = acc[mf][nf][3] + bv.y;
                *reinterpret_cast<float2*>(y + (size_t)row * OUT + col) = lo;
                *reinterpret_cast<float2*>(y + (size_t)(row + 8) * OUT + col) = hi;
            }
        }
    } else {
        for (int r = warp; r < TM; r += 8) {
            int row = n0 + r;
            float* yrow = y + (size_t)row * OUT + out0;
            for (int c = lane * 2; c < BSZ; c += 64) {
                float2 bv = *reinterpret_cast<const float2*>(bias + out0 + c);
                *reinterpret_cast<float2*>(yrow + c) = bv;
            }
        }
    }
}

// ---------------------------------------------------------------------------
extern "C" void kernel_launch(void* const* d_in, const int* in_sizes, int n_in,
                              void* d_out, int out_size) {
    const float* x      = (const float*)d_in[0];
    const float* blocks = (const float*)d_in[1];
    const float* bias   = (const float*)d_in[2];
    const int*   row_i  = (const int*)d_in[3];
    const int*   col_i  = (const int*)d_in[4];
    float*       y      = (float*)d_out;

    const int K   = in_sizes[3];
    const int OUT = in_sizes[2];
    const int IN  = XIN;
    const int N   = in_sizes[0] / IN;
    const int nrows = OUT / BSZ;

    build_csr_kernel<<<1, 1024>>>(row_i, K, nrows);

    // pre-convert x and blocks to tf32 (RNA) in device-global scratch
    static float *xc_ptr = nullptr, *bc_ptr = nullptr;
    if (!xc_ptr) {
        cudaGetSymbolAddress((void**)&xc_ptr, g_xc);
        cudaGetSymbolAddress((void**)&bc_ptr, g_bc);
    }
    cvt_kernel<<<2048, 512>>>(x, xc_ptr, in_sizes[0] / 4);
    cvt_kernel<<<1024, 512>>>(blocks, bc_ptr, in_sizes[1] / 4);

    static int attr_set = 0;
    if (!attr_set) {
        cudaFuncSetAttribute(bsl_kernel,
                             cudaFuncAttributeMaxDynamicSharedMemorySize, SMEM_BYTES);
        attr_set = 1;
    }
    dim3 grid(N / TM, nrows);
    bsl_kernel<<<grid, NTHREADS, SMEM_BYTES>>>(bias, col_i, y, IN, OUT);
}

// round 6
// speedup vs baseline: 1.3861x; 1.2817x over previous
#include <cuda_runtime.h>
#include <cstdint>

#define BSZ 64
#define TM 128
#define NTHREADS 256
#define STAGE_BYTES 24576          // A half: 128x32 f32 (16KB) + B half: 64x32 (8KB)
#define NSTAGE 3
#define SMEM_BYTES (NSTAGE * STAGE_BYTES)   // 73728 -> 3 CTAs/SM

#define XN 4096
#define XIN 4096
#define KMAX 1024

// ---------------------------------------------------------------------------
// Device-global scratch (static, no allocations).
// ---------------------------------------------------------------------------
__device__ float g_xc[(size_t)XN * XIN];          // tf32-rounded x
__device__ float g_bc[(size_t)KMAX * BSZ * BSZ];  // tf32-rounded blocks
__device__ int g_start[257];
__device__ int g_list[16384];
__device__ int g_order[256];

// ---------------------------------------------------------------------------
// CSR build + longest-first row ordering (deterministic).
// ---------------------------------------------------------------------------
__global__ void build_csr_kernel(const int* __restrict__ row_idx, int K, int nrows) {
    __shared__ int s_row[8192];
    __shared__ int s_cnt[256];
    int tid = threadIdx.x;
    for (int i = tid; i < K; i += blockDim.x) s_row[i] = row_idx[i];
    for (int i = tid; i < nrows; i += blockDim.x) s_cnt[i] = 0;
    __syncthreads();
    for (int i = tid; i < K; i += blockDim.x) atomicAdd(&s_cnt[s_row[i]], 1);
    __syncthreads();
    if (tid == 0) {
        int acc = 0;
        for (int r = 0; r < nrows; r++) { g_start[r] = acc; acc += s_cnt[r]; }
        g_start[nrows] = acc;
    }
    __syncthreads();
    for (int k = tid; k < K; k += blockDim.x) {
        int r = s_row[k];
        int rank = 0;
        for (int j = 0; j < k; j++) rank += (s_row[j] == r) ? 1 : 0;
        g_list[g_start[r] + rank] = k;
    }
    if (tid < nrows) {
        int c = s_cnt[tid];
        int rank = 0;
        for (int r2 = 0; r2 < nrows; r2++) {
            int c2 = s_cnt[r2];
            rank += (c2 > c || (c2 == c && r2 < tid)) ? 1 : 0;
        }
        g_order[rank] = tid;
    }
}

// ---------------------------------------------------------------------------
// tf32 pre-conversion (RNA), float4 grid-stride.
// ---------------------------------------------------------------------------
__device__ __forceinline__ unsigned int f2tf(unsigned int fbits) {
    unsigned int r;
    asm("cvt.rna.tf32.f32 %0, %1;" : "=r"(r) : "r"(fbits));
    return r;
}

__global__ void __launch_bounds__(512)
cvt_kernel(const float* __restrict__ src, float* __restrict__ dst, int n4) {
    int idx = blockIdx.x * blockDim.x + threadIdx.x;
    int stride = gridDim.x * blockDim.x;
    const uint4* s = reinterpret_cast<const uint4*>(src);
    uint4* d = reinterpret_cast<uint4*>(dst);
    for (int i = idx; i < n4; i += stride) {
        uint4 v = s[i];
        v.x = f2tf(v.x); v.y = f2tf(v.y); v.z = f2tf(v.z); v.w = f2tf(v.w);
        d[i] = v;
    }
}

// ---------------------------------------------------------------------------
// helpers
// ---------------------------------------------------------------------------
__device__ __forceinline__ uint32_t smem_to_u32(const void* p) {
    uint32_t a;
    asm("{ .reg .u64 t; cvta.to.shared.u64 t, %1; cvt.u32.u64 %0, t; }" : "=r"(a) : "l"(p));
    return a;
}

#define CP_ASYNC16(dst, src) \
    asm volatile("cp.async.cg.shared.global [%0], [%1], 16;" :: "r"(dst), "l"(src) : "memory")
#define CP_COMMIT() asm volatile("cp.async.commit_group;" ::: "memory")
#define CP_WAIT(n)  asm volatile("cp.async.wait_group %0;" :: "n"(n) : "memory")

#define LDSM_X4(r0, r1, r2, r3, addr) \
    asm volatile("ldmatrix.sync.aligned.m8n8.x4.shared.b16 {%0,%1,%2,%3}, [%4];" \
                 : "=r"(r0), "=r"(r1), "=r"(r2), "=r"(r3) : "r"(addr))

__device__ __forceinline__ void mma_tf32(float* c, const unsigned int* a,
                                         unsigned int b0, unsigned int b1) {
    asm volatile(
        "mma.sync.aligned.m16n8k8.row.col.f32.tf32.tf32.f32 "
        "{%0,%1,%2,%3}, {%4,%5,%6,%7}, {%8,%9}, {%0,%1,%2,%3};\n"
        : "+f"(c[0]), "+f"(c[1]), "+f"(c[2]), "+f"(c[3])
        : "r"(a[0]), "r"(a[1]), "r"(a[2]), "r"(a[3]), "r"(b0), "r"(b1));
}

// ---------------------------------------------------------------------------
// Main GEMM: CTA = (128-row x-tile, 64-col output block row).
// 3-stage cp.async ring of half-K (K=32) stages. XOR-swizzled 128B rows.
// Warp grid 4(M) x 2(N): each warp m32 x n32.
// ---------------------------------------------------------------------------
__global__ void __launch_bounds__(NTHREADS, 3)
bsl_kernel(const float* __restrict__ bias, const int* __restrict__ col_idx,
           float* __restrict__ y, int IN, int OUT) {
    extern __shared__ float smem[];
    const uint32_t sbase = smem_to_u32(smem);

    const int tid  = threadIdx.x;
    const int lane = tid & 31;
    const int warp = tid >> 5;
    const int wm   = warp & 3;    // 4 warps along M
    const int wn   = warp >> 2;   // 2 warps along N
    const int g    = lane >> 2;
    const int t    = lane & 3;

    const int n0   = blockIdx.x * TM;
    const int rblk = g_order[blockIdx.y];
    const int out0 = rblk * BSZ;

    const int beg = g_start[rblk];
    const int cnt = g_start[rblk + 1] - beg;
    const int nst = cnt * 2;

    float acc[2][4][4];
#pragma unroll
    for (int mf = 0; mf < 2; mf++)
#pragma unroll
        for (int nf = 0; nf < 4; nf++)
#pragma unroll
            for (int i = 0; i < 4; i++) acc[mf][nf][i] = 0.0f;

    // ldmatrix lane geometry: 16 rows x two 16B k-halves
    const int rl = ((lane >> 3) & 1) * 8 + (lane & 7);
    const int wb = lane >> 4;
    const int xo = lane & 7;           // == row&7 for every fragment row
    // per-kk swizzled chunk byte offsets (constant per lane)
    uint32_t cb[4];
#pragma unroll
    for (int kk = 0; kk < 4; kk++)
        cb[kk] = (uint32_t)(((2 * kk + wb) ^ xo) << 4);

    // cp.async issue geometry
    const int ld_row = tid >> 3;       // +32 per iter
    const int ld_w   = tid & 7;
    const uint32_t ld_sw = (uint32_t)(ld_w << 4);  // pre-xor applied per row below

    // stage issuer: stage s = (tile s>>1, k-half s&1)
    auto issue_stage = [&](int s) {
        const int k  = g_list[beg + (s >> 1)];
        const int c0 = col_idx[k] * BSZ + (s & 1) * 32;
        const float* xs = g_xc + (size_t)n0 * IN + c0;
        const float* bs = g_bc + (size_t)k * (BSZ * BSZ) + (s & 1) * 32;
        uint32_t buf;
        { int m3 = s % 3; buf = sbase + (uint32_t)m3 * STAGE_BYTES; }
#pragma unroll
        for (int it = 0; it < 4; it++) {           // A half: 1024 16B chunks
            int row = ld_row + it * 32;
            CP_ASYNC16(buf + (uint32_t)row * 128 + (uint32_t)(((ld_w ^ (row & 7))) << 4),
                       xs + (size_t)row * IN + ld_w * 4);
        }
#pragma unroll
        for (int it = 0; it < 2; it++) {           // B half: 512 16B chunks
            int row = ld_row + it * 32;
            CP_ASYNC16(buf + 16384 + (uint32_t)row * 128 + (uint32_t)(((ld_w ^ (row & 7))) << 4),
                       bs + (size_t)row * BSZ + ld_w * 4);
        }
    };

    // prologue: stages 0 and 1
    if (nst > 0) { issue_stage(0); CP_COMMIT(); }
    if (nst > 1) { issue_stage(1); CP_COMMIT(); }

    for (int s = 0; s < nst; s++) {
        CP_WAIT(1);            // in-order group retirement -> stage s complete
        __syncthreads();       // data visible CTA-wide; all warps done stage s-1
        if (s + 2 < nst) issue_stage(s + 2);
        CP_COMMIT();           // uniform group numbering (empty ok)

        uint32_t buf;
        { int m3 = s % 3; buf = sbase + (uint32_t)m3 * STAGE_BYTES; }
        const uint32_t a0b = buf + (uint32_t)(wm * 32 + rl) * 128;
        const uint32_t a1b = a0b + 16 * 128;
        const uint32_t b0b = buf + 16384 + (uint32_t)(wn * 32 + rl) * 128;
        const uint32_t b1b = b0b + 16 * 128;

#pragma unroll
        for (int kk = 0; kk < 4; kk++) {
            unsigned int a0[4], a1[4], b0[4], b1[4];
            LDSM_X4(a0[0], a0[1], a0[2], a0[3], a0b + cb[kk]);
            LDSM_X4(a1[0], a1[1], a1[2], a1[3], a1b + cb[kk]);
            LDSM_X4(b0[0], b0[1], b0[2], b0[3], b0b + cb[kk]);
            LDSM_X4(b1[0], b1[1], b1[2], b1[3], b1b + cb[kk]);

            mma_tf32(acc[0][0], a0, b0[0], b0[2]);
            mma_tf32(acc[1][0], a1, b0[0], b0[2]);
            mma_tf32(acc[0][1], a0, b0[1], b0[3]);
            mma_tf32(acc[1][1], a1, b0[1], b0[3]);
            mma_tf32(acc[0][2], a0, b1[0], b1[2]);
            mma_tf32(acc[1][2], a1, b1[0], b1[2]);
            mma_tf32(acc[0][3], a0, b1[1], b1[3]);
            mma_tf32(acc[1][3], a1, b1[1], b1[3]);
        }
    }

    // epilogue
    if (cnt > 0) {
#pragma unroll
        for (int mf = 0; mf < 2; mf++) {
#pragma unroll
            for (int nf = 0; nf < 4; nf++) {
                int row = n0 + wm * 32 + mf * 16 + g;
                int col = out0 + wn * 32 + nf * 8 + 2 * t;
                float2 bv = *reinterpret_cast<const float2*>(bias + col);
                float2 lo, hi;
                lo.x = acc[mf][nf][0] + bv.x;
                lo.y = acc[mf][nf][1] + bv.y;
                hi.x = acc[mf][nf][2] + bv.x;
                hi.y = acc[mf][nf][3] + bv.y;
                *reinterpret_cast<float2*>(y + (size_t)row * OUT + col) = lo;
                *reinterpret_cast<float2*>(y + (size_t)(row + 8) * OUT + col) = hi;
            }
        }
    } else {
        for (int r = warp; r < TM; r += 8) {
            int row = n0 + r;
            float* yrow = y + (size_t)row * OUT + out0;
            for (int c = lane * 2; c < BSZ; c += 64) {
                float2 bv = *reinterpret_cast<const float2*>(bias + out0 + c);
                *reinterpret_cast<float2*>(yrow + c) = bv;
            }
        }
    }
}

// ---------------------------------------------------------------------------
extern "C" void kernel_launch(void* const* d_in, const int* in_sizes, int n_in,
                              void* d_out, int out_size) {
    const float* x      = (const float*)d_in[0];
    const float* blocks = (const float*)d_in[1];
    const float* bias   = (const float*)d_in[2];
    const int*   row_i  = (const int*)d_in[3];
    const int*   col_i  = (const int*)d_in[4];
    float*       y      = (float*)d_out;

    const int K   = in_sizes[3];
    const int OUT = in_sizes[2];
    const int IN  = XIN;
    const int N   = in_sizes[0] / IN;
    const int nrows = OUT / BSZ;

    build_csr_kernel<<<1, 1024>>>(row_i, K, nrows);

    static float *xc_ptr = nullptr, *bc_ptr = nullptr;
    if (!xc_ptr) {
        cudaGetSymbolAddress((void**)&xc_ptr, g_xc);
        cudaGetSymbolAddress((void**)&bc_ptr, g_bc);
    }
    cvt_kernel<<<2048, 512>>>(x, xc_ptr, in_sizes[0] / 4);
    cvt_kernel<<<1024, 512>>>(blocks, bc_ptr, in_sizes[1] / 4);

    static int attr_set = 0;
    if (!attr_set) {
        cudaFuncSetAttribute(bsl_kernel,
                             cudaFuncAttributeMaxDynamicSharedMemorySize, SMEM_BYTES);
        attr_set = 1;
    }
    dim3 grid(N / TM, nrows);
    bsl_kernel<<<grid, NTHREADS, SMEM_BYTES>>>(bias, col_i, y, IN, OUT);
}

// round 7
// speedup vs baseline: 1.3897x; 1.0026x over previous
#include <cuda_runtime.h>
#include <cstdint>

#define BSZ 64
#define TM 128
#define NTHREADS 256
#define STAGE_BYTES 24576          // A half: 128x32 f32 (16KB) + B half: 64x32 (8KB)
#define NSTAGE 3
#define SMEM_BYTES (NSTAGE * STAGE_BYTES)   // 73728 -> 3 CTAs/SM

#define XN 4096
#define XIN 4096
#define KMAX 1024

// ---------------------------------------------------------------------------
// Device-global scratch (static, no allocations).
// ---------------------------------------------------------------------------
__device__ float g_xc[(size_t)XN * XIN];          // tf32-rounded x
__device__ float g_bc[(size_t)KMAX * BSZ * BSZ];  // tf32-rounded blocks
__device__ int g_start[257];
__device__ int g_list[16384];
__device__ int g_order[256];

// ---------------------------------------------------------------------------
// CSR build + longest-first row ordering (deterministic).
// ---------------------------------------------------------------------------
__global__ void build_csr_kernel(const int* __restrict__ row_idx, int K, int nrows) {
    __shared__ int s_row[8192];
    __shared__ int s_cnt[256];
    int tid = threadIdx.x;
    for (int i = tid; i < K; i += blockDim.x) s_row[i] = row_idx[i];
    for (int i = tid; i < nrows; i += blockDim.x) s_cnt[i] = 0;
    __syncthreads();
    for (int i = tid; i < K; i += blockDim.x) atomicAdd(&s_cnt[s_row[i]], 1);
    __syncthreads();
    if (tid == 0) {
        int acc = 0;
        for (int r = 0; r < nrows; r++) { g_start[r] = acc; acc += s_cnt[r]; }
        g_start[nrows] = acc;
    }
    __syncthreads();
    for (int k = tid; k < K; k += blockDim.x) {
        int r = s_row[k];
        int rank = 0;
        for (int j = 0; j < k; j++) rank += (s_row[j] == r) ? 1 : 0;
        g_list[g_start[r] + rank] = k;
    }
    if (tid < nrows) {
        int c = s_cnt[tid];
        int rank = 0;
        for (int r2 = 0; r2 < nrows; r2++) {
            int c2 = s_cnt[r2];
            rank += (c2 > c || (c2 == c && r2 < tid)) ? 1 : 0;
        }
        g_order[rank] = tid;
    }
}

// ---------------------------------------------------------------------------
// tf32 pre-conversion (RNA), float4 grid-stride.
// ---------------------------------------------------------------------------
__device__ __forceinline__ unsigned int f2tf(unsigned int fbits) {
    unsigned int r;
    asm("cvt.rna.tf32.f32 %0, %1;" : "=r"(r) : "r"(fbits));
    return r;
}

__global__ void __launch_bounds__(512)
cvt_kernel(const float* __restrict__ src, float* __restrict__ dst, int n4) {
    int idx = blockIdx.x * blockDim.x + threadIdx.x;
    int stride = gridDim.x * blockDim.x;
    const uint4* s = reinterpret_cast<const uint4*>(src);
    uint4* d = reinterpret_cast<uint4*>(dst);
    for (int i = idx; i < n4; i += stride) {
        uint4 v = s[i];
        v.x = f2tf(v.x); v.y = f2tf(v.y); v.z = f2tf(v.z); v.w = f2tf(v.w);
        d[i] = v;
    }
}

// ---------------------------------------------------------------------------
// helpers
// ---------------------------------------------------------------------------
__device__ __forceinline__ uint32_t smem_to_u32(const void* p) {
    uint32_t a;
    asm("{ .reg .u64 t; cvta.to.shared.u64 t, %1; cvt.u32.u64 %0, t; }" : "=r"(a) : "l"(p));
    return a;
}

#define CP_ASYNC16(dst, src) \
    asm volatile("cp.async.cg.shared.global [%0], [%1], 16;" :: "r"(dst), "l"(src) : "memory")
#define CP_COMMIT() asm volatile("cp.async.commit_group;" ::: "memory")
#define CP_WAIT(n)  asm volatile("cp.async.wait_group %0;" :: "n"(n) : "memory")

#define LDSM_X4(r0, r1, r2, r3, addr) \
    asm volatile("ldmatrix.sync.aligned.m8n8.x4.shared.b16 {%0,%1,%2,%3}, [%4];" \
                 : "=r"(r0), "=r"(r1), "=r"(r2), "=r"(r3) : "r"(addr))

__device__ __forceinline__ void mma_tf32(float* c, const unsigned int* a,
                                         unsigned int b0, unsigned int b1) {
    asm volatile(
        "mma.sync.aligned.m16n8k8.row.col.f32.tf32.tf32.f32 "
        "{%0,%1,%2,%3}, {%4,%5,%6,%7}, {%8,%9}, {%0,%1,%2,%3};\n"
        : "+f"(c[0]), "+f"(c[1]), "+f"(c[2]), "+f"(c[3])
        : "r"(a[0]), "r"(a[1]), "r"(a[2]), "r"(a[3]), "r"(b0), "r"(b1));
}

// ---------------------------------------------------------------------------
// Main GEMM: CTA = (128-row x-tile, 64-col output block row).
// 3-stage cp.async ring of half-K (K=32) stages. XOR-swizzled 128B rows.
// Warp grid 4(M) x 2(N): each warp m32 x n32.
// ---------------------------------------------------------------------------
__global__ void __launch_bounds__(NTHREADS, 3)
bsl_kernel(const float* __restrict__ bias, const int* __restrict__ col_idx,
           float* __restrict__ y, int IN, int OUT) {
    extern __shared__ float smem[];
    const uint32_t sbase = smem_to_u32(smem);

    const int tid  = threadIdx.x;
    const int lane = tid & 31;
    const int warp = tid >> 5;
    const int wm   = warp & 3;    // 4 warps along M
    const int wn   = warp >> 2;   // 2 warps along N
    const int g    = lane >> 2;
    const int t    = lane & 3;

    const int n0   = blockIdx.x * TM;
    const int rblk = g_order[blockIdx.y];
    const int out0 = rblk * BSZ;

    const int beg = g_start[rblk];
    const int cnt = g_start[rblk + 1] - beg;
    const int nst = cnt * 2;

    float acc[2][4][4];
#pragma unroll
    for (int mf = 0; mf < 2; mf++)
#pragma unroll
        for (int nf = 0; nf < 4; nf++)
#pragma unroll
            for (int i = 0; i < 4; i++) acc[mf][nf][i] = 0.0f;

    // ldmatrix lane geometry: 16 rows x two 16B k-halves
    const int rl = ((lane >> 3) & 1) * 8 + (lane & 7);
    const int wb = lane >> 4;
    const int xo = lane & 7;           // == row&7 for every fragment row
    // per-kk swizzled chunk byte offsets (constant per lane)
    uint32_t cb[4];
#pragma unroll
    for (int kk = 0; kk < 4; kk++)
        cb[kk] = (uint32_t)(((2 * kk + wb) ^ xo) << 4);

    // cp.async issue geometry
    const int ld_row = tid >> 3;       // +32 per iter
    const int ld_w   = tid & 7;
    const uint32_t ld_sw = (uint32_t)(ld_w << 4);  // pre-xor applied per row below

    // stage issuer: stage s = (tile s>>1, k-half s&1)
    auto issue_stage = [&](int s) {
        const int k  = g_list[beg + (s >> 1)];
        const int c0 = col_idx[k] * BSZ + (s & 1) * 32;
        const float* xs = g_xc + (size_t)n0 * IN + c0;
        const float* bs = g_bc + (size_t)k * (BSZ * BSZ) + (s & 1) * 32;
        uint32_t buf;
        { int m3 = s % 3; buf = sbase + (uint32_t)m3 * STAGE_BYTES; }
#pragma unroll
        for (int it = 0; it < 4; it++) {           // A half: 1024 16B chunks
            int row = ld_row + it * 32;
            CP_ASYNC16(buf + (uint32_t)row * 128 + (uint32_t)(((ld_w ^ (row & 7))) << 4),
                       xs + (size_t)row * IN + ld_w * 4);
        }
#pragma unroll
        for (int it = 0; it < 2; it++) {           // B half: 512 16B chunks
            int row = ld_row + it * 32;
            CP_ASYNC16(buf + 16384 + (uint32_t)row * 128 + (uint32_t)(((ld_w ^ (row & 7))) << 4),
                       bs + (size_t)row * BSZ + ld_w * 4);
        }
    };

    // prologue: stages 0 and 1
    if (nst > 0) { issue_stage(0); CP_COMMIT(); }
    if (nst > 1) { issue_stage(1); CP_COMMIT(); }

    for (int s = 0; s < nst; s++) {
        CP_WAIT(1);            // in-order group retirement -> stage s complete
        __syncthreads();       // data visible CTA-wide; all warps done stage s-1
        if (s + 2 < nst) issue_stage(s + 2);
        CP_COMMIT();           // uniform group numbering (empty ok)

        uint32_t buf;
        { int m3 = s % 3; buf = sbase + (uint32_t)m3 * STAGE_BYTES; }
        const uint32_t a0b = buf + (uint32_t)(wm * 32 + rl) * 128;
        const uint32_t a1b = a0b + 16 * 128;
        const uint32_t b0b = buf + 16384 + (uint32_t)(wn * 32 + rl) * 128;
        const uint32_t b1b = b0b + 16 * 128;

#pragma unroll
        for (int kk = 0; kk < 4; kk++) {
            unsigned int a0[4], a1[4], b0[4], b1[4];
            LDSM_X4(a0[0], a0[1], a0[2], a0[3], a0b + cb[kk]);
            LDSM_X4(a1[0], a1[1], a1[2], a1[3], a1b + cb[kk]);
            LDSM_X4(b0[0], b0[1], b0[2], b0[3], b0b + cb[kk]);
            LDSM_X4(b1[0], b1[1], b1[2], b1[3], b1b + cb[kk]);

            mma_tf32(acc[0][0], a0, b0[0], b0[2]);
            mma_tf32(acc[1][0], a1, b0[0], b0[2]);
            mma_tf32(acc[0][1], a0, b0[1], b0[3]);
            mma_tf32(acc[1][1], a1, b0[1], b0[3]);
            mma_tf32(acc[0][2], a0, b1[0], b1[2]);
            mma_tf32(acc[1][2], a1, b1[0], b1[2]);
            mma_tf32(acc[0][3], a0, b1[1], b1[3]);
            mma_tf32(acc[1][3], a1, b1[1], b1[3]);
        }
    }

    // epilogue
    if (cnt > 0) {
#pragma unroll
        for (int mf = 0; mf < 2; mf++) {
#pragma unroll
            for (int nf = 0; nf < 4; nf++) {
                int row = n0 + wm * 32 + mf * 16 + g;
                int col = out0 + wn * 32 + nf * 8 + 2 * t;
                float2 bv = *reinterpret_cast<const float2*>(bias + col);
                float2 lo, hi;
                lo.x = acc[mf][nf][0] + bv.x;
                lo.y = acc[mf][nf][1] + bv.y;
                hi.x = acc[mf][nf][2] + bv.x;
                hi.y = acc[mf][nf][3] + bv.y;
                *reinterpret_cast<float2*>(y + (size_t)row * OUT + col) = lo;
                *reinterpret_cast<float2*>(y + (size_t)(row + 8) * OUT + col) = hi;
            }
        }
    } else {
        for (int r = warp; r < TM; r += 8) {
            int row = n0 + r;
            float* yrow = y + (size_t)row * OUT + out0;
            for (int c = lane * 2; c < BSZ; c += 64) {
                float2 bv = *reinterpret_cast<const float2*>(bias + out0 + c);
                *reinterpret_cast<float2*>(yrow + c) = bv;
            }
        }
    }
}

// ---------------------------------------------------------------------------
extern "C" void kernel_launch(void* const* d_in, const int* in_sizes, int n_in,
                              void* d_out, int out_size) {
    const float* x      = (const float*)d_in[0];
    const float* blocks = (const float*)d_in[1];
    const float* bias   = (const float*)d_in[2];
    const int*   row_i  = (const int*)d_in[3];
    const int*   col_i  = (const int*)d_in[4];
    float*       y      = (float*)d_out;

    const int K   = in_sizes[3];
    const int OUT = in_sizes[2];
    const int IN  = XIN;
    const int N   = in_sizes[0] / IN;
    const int nrows = OUT / BSZ;

    build_csr_kernel<<<1, 1024>>>(row_i, K, nrows);

    static float *xc_ptr = nullptr, *bc_ptr = nullptr;
    if (!xc_ptr) {
        cudaGetSymbolAddress((void**)&xc_ptr, g_xc);
        cudaGetSymbolAddress((void**)&bc_ptr, g_bc);
    }
    cvt_kernel<<<2048, 512>>>(x, xc_ptr, in_sizes[0] / 4);
    cvt_kernel<<<1024, 512>>>(blocks, bc_ptr, in_sizes[1] / 4);

    static int attr_set = 0;
    if (!attr_set) {
        cudaFuncSetAttribute(bsl_kernel,
                             cudaFuncAttributeMaxDynamicSharedMemorySize, SMEM_BYTES);
        attr_set = 1;
    }
    dim3 grid(N / TM, nrows);
    bsl_kernel<<<grid, NTHREADS, SMEM_BYTES>>>(bias, col_i, y, IN, OUT);
}

// round 8
// speedup vs baseline: 2.3942x; 1.7229x over previous
#include <cuda_runtime.h>
#include <cuda_fp16.h>
#include <cstdint>

#define BSZ 64
#define TM 128
#define NTHREADS 256
#define STAGE_BYTES 24576          // full tile: A 128x64 fp16 (16KB) + B 64x64 (8KB)
#define NSTAGE 3
#define SMEM_BYTES (NSTAGE * STAGE_BYTES)   // 73728 -> 3 CTAs/SM

#define XN 4096
#define XIN 4096
#define KMAX 1024

// ---------------------------------------------------------------------------
// Device-global scratch (static, no allocations).
// ---------------------------------------------------------------------------
__device__ __half g_xh[(size_t)XN * XIN];          // fp16 x (32MB)
__device__ __half g_bh[(size_t)KMAX * BSZ * BSZ];  // fp16 blocks (8MB)
__device__ int g_start[257];
__device__ int g_list[16384];
__device__ int g_order[256];

// ---------------------------------------------------------------------------
// CSR build + longest-first row ordering (deterministic).
// ---------------------------------------------------------------------------
__global__ void build_csr_kernel(const int* __restrict__ row_idx, int K, int nrows) {
    __shared__ int s_row[8192];
    __shared__ int s_cnt[256];
    int tid = threadIdx.x;
    for (int i = tid; i < K; i += blockDim.x) s_row[i] = row_idx[i];
    for (int i = tid; i < nrows; i += blockDim.x) s_cnt[i] = 0;
    __syncthreads();
    for (int i = tid; i < K; i += blockDim.x) atomicAdd(&s_cnt[s_row[i]], 1);
    __syncthreads();
    if (tid == 0) {
        int acc = 0;
        for (int r = 0; r < nrows; r++) { g_start[r] = acc; acc += s_cnt[r]; }
        g_start[nrows] = acc;
    }
    __syncthreads();
    for (int k = tid; k < K; k += blockDim.x) {
        int r = s_row[k];
        int rank = 0;
        for (int j = 0; j < k; j++) rank += (s_row[j] == r) ? 1 : 0;
        g_list[g_start[r] + rank] = k;
    }
    if (tid < nrows) {
        int c = s_cnt[tid];
        int rank = 0;
        for (int r2 = 0; r2 < nrows; r2++) {
            int c2 = s_cnt[r2];
            rank += (c2 > c || (c2 == c && r2 < tid)) ? 1 : 0;
        }
        g_order[rank] = tid;
    }
}

// ---------------------------------------------------------------------------
// f32 -> fp16 (RN) conversion, 8 elements/thread/iter.
// ---------------------------------------------------------------------------
__global__ void __launch_bounds__(512)
cvt_half_kernel(const float4* __restrict__ src, uint4* __restrict__ dst, int n8) {
    int idx = blockIdx.x * blockDim.x + threadIdx.x;
    int stride = gridDim.x * blockDim.x;
    for (int i = idx; i < n8; i += stride) {
        float4 v0 = src[2 * i];
        float4 v1 = src[2 * i + 1];
        __half2 h0 = __floats2half2_rn(v0.x, v0.y);
        __half2 h1 = __floats2half2_rn(v0.z, v0.w);
        __half2 h2 = __floats2half2_rn(v1.x, v1.y);
        __half2 h3 = __floats2half2_rn(v1.z, v1.w);
        uint4 o;
        o.x = *reinterpret_cast<unsigned*>(&h0);
        o.y = *reinterpret_cast<unsigned*>(&h1);
        o.z = *reinterpret_cast<unsigned*>(&h2);
        o.w = *reinterpret_cast<unsigned*>(&h3);
        dst[i] = o;
    }
}

// ---------------------------------------------------------------------------
// helpers
// ---------------------------------------------------------------------------
__device__ __forceinline__ uint32_t smem_to_u32(const void* p) {
    uint32_t a;
    asm("{ .reg .u64 t; cvta.to.shared.u64 t, %1; cvt.u32.u64 %0, t; }" : "=r"(a) : "l"(p));
    return a;
}

#define CP_ASYNC16(dst, src) \
    asm volatile("cp.async.cg.shared.global [%0], [%1], 16;" :: "r"(dst), "l"(src) : "memory")
#define CP_COMMIT() asm volatile("cp.async.commit_group;" ::: "memory")
#define CP_WAIT(n)  asm volatile("cp.async.wait_group %0;" :: "n"(n) : "memory")

#define LDSM_X4(r0, r1, r2, r3, addr) \
    asm volatile("ldmatrix.sync.aligned.m8n8.x4.shared.b16 {%0,%1,%2,%3}, [%4];" \
                 : "=r"(r0), "=r"(r1), "=r"(r2), "=r"(r3) : "r"(addr))

__device__ __forceinline__ void mma_f16(float* c, const unsigned int* a,
                                        unsigned int b0, unsigned int b1) {
    asm volatile(
        "mma.sync.aligned.m16n8k16.row.col.f32.f16.f16.f32 "
        "{%0,%1,%2,%3}, {%4,%5,%6,%7}, {%8,%9}, {%0,%1,%2,%3};\n"
        : "+f"(c[0]), "+f"(c[1]), "+f"(c[2]), "+f"(c[3])
        : "r"(a[0]), "r"(a[1]), "r"(a[2]), "r"(a[3]), "r"(b0), "r"(b1));
}

// ---------------------------------------------------------------------------
// Main GEMM: CTA = (128-row x-tile, 64-col output block row).
// fp16 m16n8k16. 3-stage cp.async ring, one FULL K=64 tile per stage
// (A 128x64 fp16, 128B swizzled rows + B 64x64 fp16).
// Warp grid 4(M) x 2(N): each warp m32 x n32.
// ---------------------------------------------------------------------------
__global__ void __launch_bounds__(NTHREADS, 3)
bsl_kernel(const float* __restrict__ bias, const int* __restrict__ col_idx,
           float* __restrict__ y, int IN, int OUT) {
    extern __shared__ float smem[];
    const uint32_t sbase = smem_to_u32(smem);

    const int tid  = threadIdx.x;
    const int lane = tid & 31;
    const int warp = tid >> 5;
    const int wm   = warp & 3;    // 4 warps along M
    const int wn   = warp >> 2;   // 2 warps along N
    const int g    = lane >> 2;
    const int t    = lane & 3;

    const int n0   = blockIdx.x * TM;
    const int rblk = g_order[blockIdx.y];
    const int out0 = rblk * BSZ;

    const int beg = g_start[rblk];
    const int cnt = g_start[rblk + 1] - beg;

    float acc[2][4][4];
#pragma unroll
    for (int mf = 0; mf < 2; mf++)
#pragma unroll
        for (int nf = 0; nf < 4; nf++)
#pragma unroll
            for (int i = 0; i < 4; i++) acc[mf][nf][i] = 0.0f;

    // ---- ldmatrix lane geometry (b16 native) ----
    const int xo = lane & 7;
    // A: lane -> row (lane&15), k-chunk (lane>>4); frag mf at rows wm*32+16*mf
    const uint32_t a_row = (uint32_t)(wm * 32 + (lane & 15));
    // B: lane -> row (lane&7)+8*(lane>>4), k-chunk (lane>>3)&1; group h at rows wn*32+16*h
    const uint32_t b_row = (uint32_t)(wn * 32 + (lane & 7) + ((lane >> 4) << 3));
    uint32_t cba[4], cbb[4];
#pragma unroll
    for (int kk = 0; kk < 4; kk++) {
        cba[kk] = (uint32_t)(((2 * kk + (lane >> 4)) ^ xo) << 4);
        cbb[kk] = (uint32_t)(((2 * kk + ((lane >> 3) & 1)) ^ xo) << 4);
    }

    // cp.async issue geometry: 16B chunk = 8 fp16
    const int ld_row = tid >> 3;       // +32 per iter
    const int ld_w   = tid & 7;

    auto issue_stage = [&](int s) {
        const int k  = g_list[beg + s];
        const int c0 = col_idx[k] * BSZ;
        const __half* xs = g_xh + (size_t)n0 * IN + c0;
        const __half* bs = g_bh + (size_t)k * (BSZ * BSZ);
        const uint32_t buf = sbase + (uint32_t)(s % 3) * STAGE_BYTES;
#pragma unroll
        for (int it = 0; it < 4; it++) {           // A: 1024 chunks
            int row = ld_row + it * 32;
            CP_ASYNC16(buf + (uint32_t)row * 128 + (uint32_t)((ld_w ^ (row & 7)) << 4),
                       xs + (size_t)row * IN + ld_w * 8);
        }
#pragma unroll
        for (int it = 0; it < 2; it++) {           // B: 512 chunks
            int row = ld_row + it * 32;
            CP_ASYNC16(buf + 16384 + (uint32_t)row * 128 + (uint32_t)((ld_w ^ (row & 7)) << 4),
                       bs + (size_t)row * BSZ + ld_w * 8);
        }
    };

    if (cnt > 0) { issue_stage(0); CP_COMMIT(); }
    if (cnt > 1) { issue_stage(1); CP_COMMIT(); }

    for (int s = 0; s < cnt; s++) {
        CP_WAIT(1);            // stage s complete (s+1 may be in flight)
        __syncthreads();       // data visible; all warps done with buffer (s-1)%3
        if (s + 2 < cnt) issue_stage(s + 2);
        CP_COMMIT();           // uniform group numbering

        const uint32_t buf = sbase + (uint32_t)(s % 3) * STAGE_BYTES;
        const uint32_t a0b = buf + a_row * 128;
        const uint32_t a1b = a0b + 16 * 128;
        const uint32_t b0b = buf + 16384 + b_row * 128;
        const uint32_t b1b = b0b + 16 * 128;

#pragma unroll
        for (int kk = 0; kk < 4; kk++) {
            unsigned int a0[4], a1[4], p[4], q[4];
            LDSM_X4(a0[0], a0[1], a0[2], a0[3], a0b + cba[kk]);
            LDSM_X4(a1[0], a1[1], a1[2], a1[3], a1b + cba[kk]);
            LDSM_X4(p[0], p[1], p[2], p[3], b0b + cbb[kk]);   // n 0-15 of warp
            LDSM_X4(q[0], q[1], q[2], q[3], b1b + cbb[kk]);   // n 16-31

            mma_f16(acc[0][0], a0, p[0], p[1]);
            mma_f16(acc[1][0], a1, p[0], p[1]);
            mma_f16(acc[0][1], a0, p[2], p[3]);
            mma_f16(acc[1][1], a1, p[2], p[3]);
            mma_f16(acc[0][2], a0, q[0], q[1]);
            mma_f16(acc[1][2], a1, q[0], q[1]);
            mma_f16(acc[0][3], a0, q[2], q[3]);
            mma_f16(acc[1][3], a1, q[2], q[3]);
        }
    }

    // ---- epilogue: y = acc + bias ----
    if (cnt > 0) {
#pragma unroll
        for (int mf = 0; mf < 2; mf++) {
#pragma unroll
            for (int nf = 0; nf < 4; nf++) {
                int row = n0 + wm * 32 + mf * 16 + g;
                int col = out0 + wn * 32 + nf * 8 + 2 * t;
                float2 bv = *reinterpret_cast<const float2*>(bias + col);
                float2 lo, hi;
                lo.x = acc[mf][nf][0] + bv.x;
                lo.y = acc[mf][nf][1] + bv.y;
                hi.x = acc[mf][nf][2] + bv.x;
                hi.y = acc[mf][nf][3] + bv.y;
                *reinterpret_cast<float2*>(y + (size_t)row * OUT + col) = lo;
                *reinterpret_cast<float2*>(y + (size_t)(row + 8) * OUT + col) = hi;
            }
        }
    } else {
        for (int r = warp; r < TM; r += 8) {
            int row = n0 + r;
            float* yrow = y + (size_t)row * OUT + out0;
            for (int c = lane * 2; c < BSZ; c += 64) {
                float2 bv = *reinterpret_cast<const float2*>(bias + out0 + c);
                *reinterpret_cast<float2*>(yrow + c) = bv;
            }
        }
    }
}

// ---------------------------------------------------------------------------
extern "C" void kernel_launch(void* const* d_in, const int* in_sizes, int n_in,
                              void* d_out, int out_size) {
    const float* x      = (const float*)d_in[0];
    const float* blocks = (const float*)d_in[1];
    const float* bias   = (const float*)d_in[2];
    const int*   row_i  = (const int*)d_in[3];
    const int*   col_i  = (const int*)d_in[4];
    float*       y      = (float*)d_out;

    const int K   = in_sizes[3];
    const int OUT = in_sizes[2];
    const int IN  = XIN;
    const int N   = in_sizes[0] / IN;
    const int nrows = OUT / BSZ;

    build_csr_kernel<<<1, 1024>>>(row_i, K, nrows);

    static __half *xh_ptr = nullptr, *bh_ptr = nullptr;
    if (!xh_ptr) {
        cudaGetSymbolAddress((void**)&xh_ptr, g_xh);
        cudaGetSymbolAddress((void**)&bh_ptr, g_bh);
    }
    cvt_half_kernel<<<2048, 512>>>((const float4*)x, (uint4*)xh_ptr, in_sizes[0] / 8);
    cvt_half_kernel<<<1024, 512>>>((const float4*)blocks, (uint4*)bh_ptr, in_sizes[1] / 8);

    static int attr_set = 0;
    if (!attr_set) {
        cudaFuncSetAttribute(bsl_kernel,
                             cudaFuncAttributeMaxDynamicSharedMemorySize, SMEM_BYTES);
        attr_set = 1;
    }
    dim3 grid(N / TM, nrows);
    bsl_kernel<<<grid, NTHREADS, SMEM_BYTES>>>(bias, col_i, y, IN, OUT);
}

// round 10
// speedup vs baseline: 2.5217x; 1.0532x over previous
#include <cuda_runtime.h>
#include <cuda_fp16.h>
#include <cstdint>

#define BSZ 64
#define TM 256                      // CTA rows
#define NTHREADS 256
#define STAGE_BYTES 40960           // A 256x64 fp16 (32KB) + B 64x64 fp16 (8KB)
#define SMEM_BYTES (2 * STAGE_BYTES)  // 81920 -> 2 CTAs/SM

#define XN 4096
#define XIN 4096
#define KMAX 1024

// ---------------------------------------------------------------------------
// Device-global scratch (static, no allocations).
// ---------------------------------------------------------------------------
__device__ __half g_xh[(size_t)XN * XIN];          // fp16 x (32MB)
__device__ __half g_bh[(size_t)KMAX * BSZ * BSZ];  // fp16 blocks (8MB)
__device__ int g_start[257];
__device__ int g_list[16384];
__device__ int g_order[256];

// ---------------------------------------------------------------------------
// CSR build + longest-first row ordering (deterministic).
// ---------------------------------------------------------------------------
__global__ void build_csr_kernel(const int* __restrict__ row_idx, int K, int nrows) {
    __shared__ int s_row[8192];
    __shared__ int s_cnt[256];
    int tid = threadIdx.x;
    for (int i = tid; i < K; i += blockDim.x) s_row[i] = row_idx[i];
    for (int i = tid; i < nrows; i += blockDim.x) s_cnt[i] = 0;
    __syncthreads();
    for (int i = tid; i < K; i += blockDim.x) atomicAdd(&s_cnt[s_row[i]], 1);
    __syncthreads();
    if (tid == 0) {
        int acc = 0;
        for (int r = 0; r < nrows; r++) { g_start[r] = acc; acc += s_cnt[r]; }
        g_start[nrows] = acc;
    }
    __syncthreads();
    for (int k = tid; k < K; k += blockDim.x) {
        int r = s_row[k];
        int rank = 0;
        for (int j = 0; j < k; j++) rank += (s_row[j] == r) ? 1 : 0;
        g_list[g_start[r] + rank] = k;
    }
    if (tid < nrows) {
        int c = s_cnt[tid];
        int rank = 0;
        for (int r2 = 0; r2 < nrows; r2++) {
            int c2 = s_cnt[r2];
            rank += (c2 > c || (c2 == c && r2 < tid)) ? 1 : 0;
        }
        g_order[rank] = tid;
    }
}

// ---------------------------------------------------------------------------
// Fused f32 -> fp16 (RN) conversion for x and blocks in one launch.
// ---------------------------------------------------------------------------
__global__ void __launch_bounds__(512)
cvt_half_fused(const float4* __restrict__ xsrc, uint4* __restrict__ xdst, int xn8,
               const float4* __restrict__ bsrc, uint4* __restrict__ bdst, int bn8) {
    int idx = blockIdx.x * blockDim.x + threadIdx.x;
    int stride = gridDim.x * blockDim.x;
    int total = xn8 + bn8;
    for (int i = idx; i < total; i += stride) {
        const float4* s; uint4* d; int j;
        if (i < xn8) { s = xsrc; d = xdst; j = i; }
        else         { s = bsrc; d = bdst; j = i - xn8; }
        float4 v0 = s[2 * j];
        float4 v1 = s[2 * j + 1];
        __half2 h0 = __floats2half2_rn(v0.x, v0.y);
        __half2 h1 = __floats2half2_rn(v0.z, v0.w);
        __half2 h2 = __floats2half2_rn(v1.x, v1.y);
        __half2 h3 = __floats2half2_rn(v1.z, v1.w);
        uint4 o;
        o.x = *reinterpret_cast<unsigned*>(&h0);
        o.y = *reinterpret_cast<unsigned*>(&h1);
        o.z = *reinterpret_cast<unsigned*>(&h2);
        o.w = *reinterpret_cast<unsigned*>(&h3);
        d[j] = o;
    }
}

// ---------------------------------------------------------------------------
// helpers
// ---------------------------------------------------------------------------
__device__ __forceinline__ uint32_t smem_to_u32(const void* p) {
    uint32_t a;
    asm("{ .reg .u64 t; cvta.to.shared.u64 t, %1; cvt.u32.u64 %0, t; }" : "=r"(a) : "l"(p));
    return a;
}

#define CP_ASYNC16(dst, src) \
    asm volatile("cp.async.cg.shared.global [%0], [%1], 16;" :: "r"(dst), "l"(src) : "memory")
#define CP_COMMIT() asm volatile("cp.async.commit_group;" ::: "memory")
#define CP_WAIT(n)  asm volatile("cp.async.wait_group %0;" :: "n"(n) : "memory")

#define LDSM_X4(r0, r1, r2, r3, addr) \
    asm volatile("ldmatrix.sync.aligned.m8n8.x4.shared.b16 {%0,%1,%2,%3}, [%4];" \
                 : "=r"(r0), "=r"(r1), "=r"(r2), "=r"(r3) : "r"(addr))

__device__ __forceinline__ void mma_f16(float* c, const unsigned int* a,
                                        unsigned int b0, unsigned int b1) {
    asm volatile(
        "mma.sync.aligned.m16n8k16.row.col.f32.f16.f16.f32 "
        "{%0,%1,%2,%3}, {%4,%5,%6,%7}, {%8,%9}, {%0,%1,%2,%3};\n"
        : "+f"(c[0]), "+f"(c[1]), "+f"(c[2]), "+f"(c[3])
        : "r"(a[0]), "r"(a[1]), "r"(a[2]), "r"(a[3]), "r"(b0), "r"(b1));
}

// ---------------------------------------------------------------------------
// Main GEMM: CTA = (256-row x-tile, 64-col output block row).
// Warp grid 4(M) x 2(N): each warp m64 x n32 (acc 64 f32/thread).
// 2-stage cp.async double buffer, full K=64 tile per stage.
// ---------------------------------------------------------------------------
__global__ void __launch_bounds__(NTHREADS, 2)
bsl_kernel(const float* __restrict__ bias, const int* __restrict__ col_idx,
           float* __restrict__ y, int IN, int OUT) {
    extern __shared__ float smem[];
    const uint32_t sbase = smem_to_u32(smem);

    const int tid  = threadIdx.x;
    const int lane = tid & 31;
    const int warp = tid >> 5;
    const int wm   = warp & 3;    // 4 warps along M (64 rows each)
    const int wn   = warp >> 2;   // 2 warps along N (32 cols each)
    const int g    = lane >> 2;
    const int t    = lane & 3;

    const int n0   = blockIdx.x * TM;
    const int rblk = g_order[blockIdx.y];
    const int out0 = rblk * BSZ;

    const int beg = g_start[rblk];
    const int cnt = g_start[rblk + 1] - beg;

    float acc[4][4][4];
#pragma unroll
    for (int mf = 0; mf < 4; mf++)
#pragma unroll
        for (int nf = 0; nf < 4; nf++)
#pragma unroll
            for (int i = 0; i < 4; i++) acc[mf][nf][i] = 0.0f;

    // ---- ldmatrix lane geometry (b16 native) ----
    const int xo = lane & 7;
    const uint32_t a_row = (uint32_t)(wm * 64 + (lane & 15));             // + mf*16
    const uint32_t b_row = (uint32_t)(wn * 32 + (lane & 7) + ((lane >> 4) << 3));
    uint32_t cba[4], cbb[4];
#pragma unroll
    for (int kk = 0; kk < 4; kk++) {
        cba[kk] = (uint32_t)(((2 * kk + (lane >> 4)) ^ xo) << 4);
        cbb[kk] = (uint32_t)(((2 * kk + ((lane >> 3) & 1)) ^ xo) << 4);
    }

    // cp.async issue geometry: 16B chunk = 8 fp16
    const int ld_row = tid >> 3;       // +32 per iter
    const int ld_w   = tid & 7;

    auto issue_stage = [&](int s) {
        const int k  = g_list[beg + s];
        const int c0 = col_idx[k] * BSZ;
        const __half* xs = g_xh + (size_t)n0 * IN + c0;
        const __half* bs = g_bh + (size_t)k * (BSZ * BSZ);
        const uint32_t buf = sbase + (uint32_t)(s & 1) * STAGE_BYTES;
#pragma unroll
        for (int it = 0; it < 8; it++) {           // A: 2048 chunks (256 rows)
            int row = ld_row + it * 32;
            CP_ASYNC16(buf + (uint32_t)row * 128 + (uint32_t)((ld_w ^ (row & 7)) << 4),
                       xs + (size_t)row * IN + ld_w * 8);
        }
#pragma unroll
        for (int it = 0; it < 2; it++) {           // B: 512 chunks
            int row = ld_row + it * 32;
            CP_ASYNC16(buf + 32768 + (uint32_t)row * 128 + (uint32_t)((ld_w ^ (row & 7)) << 4),
                       bs + (size_t)row * BSZ + ld_w * 8);
        }
    };

    if (cnt > 0) { issue_stage(0); CP_COMMIT(); }

    for (int s = 0; s < cnt; s++) {
        if (s + 1 < cnt) { issue_stage(s + 1); CP_COMMIT(); CP_WAIT(1); }
        else             { CP_WAIT(0); }
        __syncthreads();   // stage s data visible to all warps

        const uint32_t buf = sbase + (uint32_t)(s & 1) * STAGE_BYTES;
        const uint32_t ab  = buf + a_row * 128;
        const uint32_t b0b = buf + 32768 + b_row * 128;
        const uint32_t b1b = b0b + 16 * 128;

#pragma unroll
        for (int kk = 0; kk < 4; kk++) {
            unsigned int a[4][4], p[4], q[4];
#pragma unroll
            for (int mf = 0; mf < 4; mf++)
                LDSM_X4(a[mf][0], a[mf][1], a[mf][2], a[mf][3],
                        ab + (uint32_t)(mf * 16 * 128) + cba[kk]);
            LDSM_X4(p[0], p[1], p[2], p[3], b0b + cbb[kk]);   // n 0-15
            LDSM_X4(q[0], q[1], q[2], q[3], b1b + cbb[kk]);   // n 16-31

#pragma unroll
            for (int mf = 0; mf < 4; mf++) {
                mma_f16(acc[mf][0], a[mf], p[0], p[1]);
                mma_f16(acc[mf][1], a[mf], p[2], p[3]);
                mma_f16(acc[mf][2], a[mf], q[0], q[1]);
                mma_f16(acc[mf][3], a[mf], q[2], q[3]);
            }
        }
        __syncthreads();   // all warps done with buf before it is refilled
    }

    // ---- epilogue: y = acc + bias ----
    if (cnt > 0) {
#pragma unroll
        for (int mf = 0; mf < 4; mf++) {
#pragma unroll
            for (int nf = 0; nf < 4; nf++) {
                int row = n0 + wm * 64 + mf * 16 + g;
                int col = out0 + wn * 32 + nf * 8 + 2 * t;
                float2 bv = *reinterpret_cast<const float2*>(bias + col);
                float2 lo, hi;
                lo.x = acc[mf][nf][0] + bv.x;
                lo.y = acc[mf][nf][1] + bv.y;
                hi.x = acc[mf][nf][2] + bv.x;
                hi.y = acc[mf][nf][3] + bv.y;
                *reinterpret_cast<float2*>(y + (size_t)row * OUT + col) = lo;
                *reinterpret_cast<float2*>(y + (size_t)(row + 8) * OUT + col) = hi;
            }
        }
    } else {
        for (int r = warp; r < TM; r += 8) {
            int row = n0 + r;
            float* yrow = y + (size_t)row * OUT + out0;
            for (int c = lane * 2; c < BSZ; c += 64) {
                float2 bv = *reinterpret_cast<const float2*>(bias + out0 + c);
                *reinterpret_cast<float2*>(yrow + c) = bv;
            }
        }
    }
}

// ---------------------------------------------------------------------------
extern "C" void kernel_launch(void* const* d_in, const int* in_sizes, int n_in,
                              void* d_out, int out_size) {
    const float* x      = (const float*)d_in[0];
    const float* blocks = (const float*)d_in[1];
    const float* bias   = (const float*)d_in[2];
    const int*   row_i  = (const int*)d_in[3];
    const int*   col_i  = (const int*)d_in[4];
    float*       y      = (float*)d_out;

    const int K   = in_sizes[3];
    const int OUT = in_sizes[2];
    const int IN  = XIN;
    const int N   = in_sizes[0] / IN;
    const int nrows = OUT / BSZ;

    build_csr_kernel<<<1, 1024>>>(row_i, K, nrows);

    static __half *xh_ptr = nullptr, *bh_ptr = nullptr;
    if (!xh_ptr) {
        cudaGetSymbolAddress((void**)&xh_ptr, g_xh);
        cudaGetSymbolAddress((void**)&bh_ptr, g_bh);
    }
    cvt_half_fused<<<2304, 512>>>((const float4*)x, (uint4*)xh_ptr, in_sizes[0] / 8,
                                  (const float4*)blocks, (uint4*)bh_ptr, in_sizes[1] / 8);

    static int attr_set = 0;
    if (!attr_set) {
        cudaFuncSetAttribute(bsl_kernel,
                             cudaFuncAttributeMaxDynamicSharedMemorySize, SMEM_BYTES);
        attr_set = 1;
    }
    dim3 grid(N / TM, nrows);
    bsl_kernel<<<grid, NTHREADS, SMEM_BYTES>>>(bias, col_i, y, IN, OUT);
}